// round 13
// baseline (speedup 1.0000x reference)
#include <cuda_runtime.h>
#include <cuda_bf16.h>
#include <math.h>
#include <float.h>
#include <stdint.h>

#define FS        16000.0f
#define N_FILT    80
#define FILT_DIM  251
#define HALF_K    125
#define L_IN      32000
#define L_OUT     (L_IN - FILT_DIM + 1)   // 31750
#define BATCH     32

#define KF        128
#define KSTEPS    8
#define NT        10
#define MTILE     128
#define NLT       ((L_OUT + MTILE - 1) / MTILE)   // 249
#define THREADS   256
#define DSTRIDE   132                     // padded row stride (floats)

// Folded H fragment-packed: [kstep][ntile][lane] -> uint4
//   .x = hi b0   .y = hi b1 (k+8)   .z = lo b0   .w = lo b1
__device__ __align__(16) uint4 Hfrag_g[KSTEPS][NT][32];

union Smem {
    struct {
        float xf0[258];   // X(l0 + i)
        float xf1[258];   // X(l0 + i + 1)
        float xr0[258];   // X(l0 + 377 - i)
        float xr1[258];   // X(l0 + 376 - i)
    } x;
    float dstage[N_FILT][DSTRIDE];        // 42240 B (epilogue)
};

// ---------------------------------------------------------------------------
__device__ __forceinline__ void mma16816(float d[4],
                                         uint32_t a0, uint32_t a1,
                                         uint32_t a2, uint32_t a3,
                                         uint32_t b0, uint32_t b1) {
    asm volatile(
        "mma.sync.aligned.m16n8k16.row.col.f32.bf16.bf16.f32 "
        "{%0,%1,%2,%3}, {%4,%5,%6,%7}, {%8,%9}, {%0,%1,%2,%3};"
        : "+f"(d[0]), "+f"(d[1]), "+f"(d[2]), "+f"(d[3])
        : "r"(a0), "r"(a1), "r"(a2), "r"(a3), "r"(b0), "r"(b1));
}

// s-pair -> (hi bf16x2, lo bf16x2). lo captures the bf16 remainder.
__device__ __forceinline__ void mk_frag(uint32_t& hi, uint32_t& lo,
                                        float2 a, float2 b) {
    float sx = a.x + b.x;
    float sy = a.y + b.y;
    uint32_t h;
    asm("cvt.rn.bf16x2.f32 %0, %1, %2;" : "=r"(h) : "f"(sy), "f"(sx));
    float hx = __uint_as_float(h << 16);
    float hy = __uint_as_float(h & 0xFFFF0000u);
    float ex = sx - hx;
    float ey = sy - hy;
    asm("cvt.rn.bf16x2.f32 %0, %1, %2;" : "=r"(lo) : "f"(ey), "f"(ex));
    hi = h;
}

// ---------------------------------------------------------------------------
// Kernel 1: build FOLDED taps (reference numerics; averaged window pair).
// H'[125] = center/2 because the uniform pair formula gives s(125) = 2x.
// ---------------------------------------------------------------------------
__global__ void build_filters_kernel(const float* __restrict__ norm_f1,
                                     const float* __restrict__ norm_f2,
                                     const float* __restrict__ amplitude)
{
    const int f = blockIdx.x;
    const int t = threadIdx.x;

    const float min_n = 50.0f / FS;
    float f1n = fabsf(norm_f1[f]) + min_n;
    float f2n = f1n + fabsf(norm_f2[f] - f1n) + min_n;
    float f1 = f1n * FS;
    float f2 = f2n * FS;
    float amp = fabsf(amplitude[f]);

    __shared__ float bp[HALF_K];
    __shared__ float red[128];

    const float TWO_PI = 6.283185307179586f;

    float v = -FLT_MAX;
    if (t < HALF_K) {
        float tr = (float)(t + 1) / FS;          // exact integers 1..125 / fs
        float a2 = TWO_PI * f2 * tr;             // fp32 arg like reference
        float a1 = TWO_PI * f1 * tr;
        float s2 = (float)(sin((double)a2) / (double)a2);
        float s1 = (float)(sin((double)a1) / (double)a1);
        float bb = amp * (2.0f * f2 * s2 - 2.0f * f1 * s1);
        bp[t] = bb;
        v = bb;
    }
    float center = amp * (2.0f * f2 - 2.0f * f1);
    v = fmaxf(v, center);

    red[t] = v;
    __syncthreads();
    for (int s = 64; s > 0; s >>= 1) {
        if (t < s) red[t] = fmaxf(red[t], red[t + s]);
        __syncthreads();
    }
    float mx = red[0];

    const int nt   = f >> 3;
    const int lrow = f & 7;

    for (int k = t; k < KF; k += blockDim.x) {
        float hv = 0.0f;
        if (k < HALF_K) {
            double wj  = 0.54 - 0.46 * cos(2.0 * M_PI * (double)k / 250.0);
            double wjm = 0.54 - 0.46 * cos(2.0 * M_PI * (double)(250 - k) / 250.0);
            hv = (bp[HALF_K - 1 - k] / mx) * (float)(0.5 * (wj + wjm));
        } else if (k == HALF_K) {
            hv = 0.5f * (center / mx);           // s(125) = 2x -> halve tap
        }
        __nv_bfloat16 hi = __float2bfloat16(hv);
        __nv_bfloat16 lo = __float2bfloat16(hv - __bfloat162float(hi));

        int ks = k >> 4, kk = k & 15;
        int bsel = kk >> 3;
        int q    = (kk >> 1) & 3;
        int e    = kk & 1;
        int lane = lrow * 4 + q;

        __nv_bfloat16* dst = (__nv_bfloat16*)&Hfrag_g[ks][nt][lane];
        dst[bsel * 2 + e]     = hi;    // .x/.y
        dst[4 + bsel * 2 + e] = lo;    // .z/.w
    }
}

// ---------------------------------------------------------------------------
// Kernel 2: folded implicit-GEMM, A-fragments built in registers, coalesced
// smem-staged epilogue (STG.64 — filter rows are only 8B aligned).
// CTA: 1 batch x 128 l x 80 f, 8 warps. Warp w = (mp = w&3, nh = w>>2):
// m-tiles {2mp, 2mp+1}, n-tiles [5nh, 5nh+5). B straight from global.
// ---------------------------------------------------------------------------
__global__ void __launch_bounds__(THREADS, 2)
sinc_conv_kernel(const float* __restrict__ x, float* __restrict__ out)
{
    extern __shared__ __align__(16) Smem S[];

    const int b    = blockIdx.y;
    const int l0   = blockIdx.x * MTILE;
    const int tid  = threadIdx.x;
    const int w    = tid >> 5;
    const int lane = tid & 31;

    // ---- stage forward + reversed (and +1 shifted) x copies, clamped ----
    {
        const float* xb = x + (size_t)b * L_IN;
        for (int i = tid; i < 256; i += THREADS) {
            int gf = l0 + i;
            S->x.xf0[i] = (gf < L_IN) ? xb[gf] : 0.0f;
            S->x.xf1[i] = (gf + 1 < L_IN) ? xb[gf + 1] : 0.0f;
            int gr = l0 + 377 - i;
            S->x.xr0[i] = (gr < L_IN) ? xb[gr] : 0.0f;
            int g2 = l0 + 376 - i;
            S->x.xr1[i] = (g2 < L_IN) ? xb[g2] : 0.0f;
        }
    }
    __syncthreads();

    const int mp  = w & 3;
    const int nh  = w >> 2;
    const int gid = lane >> 2;
    const int tig = lane & 3;
    const int par = gid & 1;        // parity of r (16*mt even)
    const int qq  = 1 - par;        // parity of rev index

    const int rA  = 32 * mp + gid;  // row of m-tile 2mp for this lane

    const float2* Xf = (const float2*)(par ? S->x.xf1 : S->x.xf0);
    const float2* Xr = (const float2*)(qq ? S->x.xr1 : S->x.xr0);

    float D[2][5][4];
    #pragma unroll
    for (int m = 0; m < 2; m++)
        #pragma unroll
        for (int n = 0; n < 5; n++)
            #pragma unroll
            for (int e = 0; e < 4; e++)
                D[m][n][e] = 0.0f;

    #pragma unroll 1
    for (int ks = 0; ks < KSTEPS; ks++) {
        const int k0 = 16 * ks + 2 * tig;
        const int vb = (rA - par + k0) >> 1;            // fwd f2 word of v = rA+k0
        const int ub = (127 - rA + k0 - 24 - qq) >> 1;  // rev f2 word of u-24

        float2 F0 = Xf[vb],      F1 = Xf[vb + 4],  F2 = Xf[vb + 8];
        float2 F3 = Xf[vb + 12], F4 = Xf[vb + 16];
        float2 R0 = Xr[ub],      R1 = Xr[ub + 4],  R2 = Xr[ub + 8];
        float2 R3 = Xr[ub + 12], R4 = Xr[ub + 16];

        uint4 Ah0, Al0, Ah1, Al1;
        mk_frag(Ah0.x, Al0.x, F0, R3);   // (r,   k0)
        mk_frag(Ah0.y, Al0.y, F1, R2);   // (r+8, k0)
        mk_frag(Ah0.z, Al0.z, F1, R4);   // (r,   k0+8)
        mk_frag(Ah0.w, Al0.w, F2, R3);   // (r+8, k0+8)
        mk_frag(Ah1.x, Al1.x, F2, R1);
        mk_frag(Ah1.y, Al1.y, F3, R0);
        mk_frag(Ah1.z, Al1.z, F3, R2);
        mk_frag(Ah1.w, Al1.w, F4, R1);

        const uint4* __restrict__ Hp = &Hfrag_g[ks][5 * nh][lane];
        #pragma unroll
        for (int n = 0; n < 5; n++) {
            uint4 Bf = Hp[n * 32];          // LDG.128, L1/L2-hot
            mma16816(D[0][n], Ah0.x, Ah0.y, Ah0.z, Ah0.w, Bf.x, Bf.y);  // hh*sh
            mma16816(D[0][n], Al0.x, Al0.y, Al0.z, Al0.w, Bf.x, Bf.y);  // hh*sl
            mma16816(D[0][n], Ah0.x, Ah0.y, Ah0.z, Ah0.w, Bf.z, Bf.w);  // hl*sh
            mma16816(D[1][n], Ah1.x, Ah1.y, Ah1.z, Ah1.w, Bf.x, Bf.y);
            mma16816(D[1][n], Al1.x, Al1.y, Al1.z, Al1.w, Bf.x, Bf.y);
            mma16816(D[1][n], Ah1.x, Ah1.y, Ah1.z, Ah1.w, Bf.z, Bf.w);
        }
    }

    // ---- epilogue: stage D to smem (conflict-free), then coalesced STG.64 ----
    __syncthreads();   // all x reads done; union flips to dstage
    {
        const int rp = lane >> 2;
        const int q  = lane & 3;
        #pragma unroll
        for (int m = 0; m < 2; m++) {
            const int ll = 16 * (2 * mp + m) + rp;
            #pragma unroll
            for (int n = 0; n < 5; n++) {
                const int f = (5 * nh + n) * 8 + q * 2;
                S->dstage[f][ll]         = D[m][n][0];
                S->dstage[f + 1][ll]     = D[m][n][1];
                S->dstage[f][ll + 8]     = D[m][n][2];
                S->dstage[f + 1][ll + 8] = D[m][n][3];
            }
        }
    }
    __syncthreads();

    {
        float* ob = out + (size_t)b * N_FILT * L_OUT;
        const bool full = (l0 + MTILE) <= L_OUT;
        // 80 rows x 64 float2 = 5120 slots; 256 threads x 20
        #pragma unroll
        for (int i = 0; i < 20; i++) {
            int slot = tid + i * THREADS;
            int f = slot >> 6;
            int c = slot & 63;
            float2 v = *(const float2*)&S->dstage[f][2 * c];
            int l = l0 + 2 * c;
            float* op = ob + (size_t)f * L_OUT;
            if (full) {
                *(float2*)(op + l) = v;        // rows are 8B aligned
            } else {
                if (l     < L_OUT) op[l]     = v.x;
                if (l + 1 < L_OUT) op[l + 1] = v.y;
            }
        }
    }
}

// ---------------------------------------------------------------------------
extern "C" void kernel_launch(void* const* d_in, const int* in_sizes, int n_in,
                              void* d_out, int out_size)
{
    const float* x       = (const float*)d_in[0];
    const float* norm_f1 = (const float*)d_in[1];
    const float* norm_f2 = (const float*)d_in[2];
    const float* ampl    = (const float*)d_in[3];
    float* out = (float*)d_out;

    cudaFuncSetAttribute(sinc_conv_kernel,
                         cudaFuncAttributeMaxDynamicSharedMemorySize,
                         (int)sizeof(Smem));

    build_filters_kernel<<<N_FILT, 128>>>(norm_f1, norm_f2, ampl);

    dim3 grid(NLT, BATCH);   // (249, 32)
    sinc_conv_kernel<<<grid, THREADS, sizeof(Smem)>>>(x, out);
}

// round 14
// speedup vs baseline: 1.3126x; 1.3126x over previous
#include <cuda_runtime.h>
#include <cuda_fp16.h>
#include <math.h>
#include <float.h>
#include <stdint.h>

#define FS        16000.0f
#define N_FILT    80
#define FILT_DIM  251
#define HALF_K    125
#define L_IN      32000
#define L_OUT     (L_IN - FILT_DIM + 1)   // 31750
#define BATCH     32

#define KF        128
#define KSTEPS    8
#define NT        10
#define MTILE     128
#define NLT       ((L_OUT + MTILE - 1) / MTILE)   // 249
#define THREADS   256

// bank-stagger offsets (floats): word(XF1)-word(XF0) = 136 = 8 mod 16 -> the
// parity pair's 7-word windows are disjoint mod 16 banks (conflict-free LDS)
#define XF0       0
#define XF1       272
#define XR0       544
#define XR1       816
#define XBUF_LEN  1088

// Folded H (fp16, unsplit): [kstep][ntile][lane] -> uint2 {b0, b1}
// b0 = (H'[f][16ks+2q], H'[f][16ks+2q+1]), b1 = same k+8; f = 8*nt + (lane>>2)
__device__ __align__(16) uint2 Hfrag_g[KSTEPS][NT][32];

struct Smem { float xbuf[XBUF_LEN]; };

// ---------------------------------------------------------------------------
__device__ __forceinline__ void mma16816(float d[4],
                                         uint32_t a0, uint32_t a1,
                                         uint32_t a2, uint32_t a3,
                                         uint32_t b0, uint32_t b1) {
    asm volatile(
        "mma.sync.aligned.m16n8k16.row.col.f32.f16.f16.f32 "
        "{%0,%1,%2,%3}, {%4,%5,%6,%7}, {%8,%9}, {%0,%1,%2,%3};"
        : "+f"(d[0]), "+f"(d[1]), "+f"(d[2]), "+f"(d[3])
        : "r"(a0), "r"(a1), "r"(a2), "r"(a3), "r"(b0), "r"(b1));
}

// s-pair -> (hi f16x2, lo f16x2). lo captures the fp16 remainder of s.
__device__ __forceinline__ void mk_frag(uint32_t& hi, uint32_t& lo,
                                        float2 a, float2 b) {
    float sx = a.x + b.x;
    float sy = a.y + b.y;
    __half2 h2 = __float22half2_rn(make_float2(sx, sy));   // .x -> low 16 bits
    float2 hf = __half22float2(h2);
    __half2 l2 = __float22half2_rn(make_float2(sx - hf.x, sy - hf.y));
    hi = *(uint32_t*)&h2;
    lo = *(uint32_t*)&l2;
}

// ---------------------------------------------------------------------------
// Kernel 1: build FOLDED taps (reference numerics; averaged window pair),
// cast to fp16 (no split), packed fragment-linear.
// H'[125] = center/2 because the uniform pair formula gives s(125) = 2x.
// ---------------------------------------------------------------------------
__global__ void build_filters_kernel(const float* __restrict__ norm_f1,
                                     const float* __restrict__ norm_f2,
                                     const float* __restrict__ amplitude)
{
    const int f = blockIdx.x;
    const int t = threadIdx.x;

    const float min_n = 50.0f / FS;
    float f1n = fabsf(norm_f1[f]) + min_n;
    float f2n = f1n + fabsf(norm_f2[f] - f1n) + min_n;
    float f1 = f1n * FS;
    float f2 = f2n * FS;
    float amp = fabsf(amplitude[f]);

    __shared__ float bp[HALF_K];
    __shared__ float red[128];

    const float TWO_PI = 6.283185307179586f;

    float v = -FLT_MAX;
    if (t < HALF_K) {
        float tr = (float)(t + 1) / FS;          // exact integers 1..125 / fs
        float a2 = TWO_PI * f2 * tr;             // fp32 arg like reference
        float a1 = TWO_PI * f1 * tr;
        float s2 = (float)(sin((double)a2) / (double)a2);
        float s1 = (float)(sin((double)a1) / (double)a1);
        float bb = amp * (2.0f * f2 * s2 - 2.0f * f1 * s1);
        bp[t] = bb;
        v = bb;
    }
    float center = amp * (2.0f * f2 - 2.0f * f1);
    v = fmaxf(v, center);

    red[t] = v;
    __syncthreads();
    for (int s = 64; s > 0; s >>= 1) {
        if (t < s) red[t] = fmaxf(red[t], red[t + s]);
        __syncthreads();
    }
    float mx = red[0];

    const int nt   = f >> 3;
    const int lrow = f & 7;

    for (int k = t; k < KF; k += blockDim.x) {
        float hv = 0.0f;
        if (k < HALF_K) {
            double wj  = 0.54 - 0.46 * cos(2.0 * M_PI * (double)k / 250.0);
            double wjm = 0.54 - 0.46 * cos(2.0 * M_PI * (double)(250 - k) / 250.0);
            hv = (bp[HALF_K - 1 - k] / mx) * (float)(0.5 * (wj + wjm));
        } else if (k == HALF_K) {
            hv = 0.5f * (center / mx);           // s(125) = 2x -> halve tap
        }
        __half hh = __float2half_rn(hv);

        int ks = k >> 4, kk = k & 15;
        int bsel = kk >> 3;
        int q    = (kk >> 1) & 3;
        int e    = kk & 1;
        int lane = lrow * 4 + q;

        __half* dst = (__half*)&Hfrag_g[ks][nt][lane];
        dst[bsel * 2 + e] = hh;     // uint2 = 4 halves: b0.lo,b0.hi,b1.lo,b1.hi
    }
}

// ---------------------------------------------------------------------------
// Kernel 2: folded implicit-GEMM via mma.sync m16n8k16 fp16 (2-pass x-split).
// CTA: 1 batch x 128 l x 80 f, 8 warps. Warp w = (mp = w&3, nh = w>>2):
// m-tiles {2mp, 2mp+1}, n-tiles [5nh, 5nh+5). B (fp16, uint2) from global.
// Bank-staggered parity x copies make every window LDS.64 one wavefront.
// ---------------------------------------------------------------------------
__global__ void __launch_bounds__(THREADS, 2)
sinc_conv_kernel(const float* __restrict__ x, float* __restrict__ out)
{
    extern __shared__ __align__(16) Smem S[];
    float* xbuf = S->xbuf;

    const int b    = blockIdx.y;
    const int l0   = blockIdx.x * MTILE;
    const int tid  = threadIdx.x;
    const int w    = tid >> 5;
    const int lane = tid & 31;

    // ---- stage forward + reversed (and +1 shifted) x copies, clamped ----
    {
        const float* xb = x + (size_t)b * L_IN;
        for (int i = tid; i < 256; i += THREADS) {
            int gf = l0 + i;
            xbuf[XF0 + i] = (gf < L_IN) ? xb[gf] : 0.0f;
            xbuf[XF1 + i] = (gf + 1 < L_IN) ? xb[gf + 1] : 0.0f;
            int gr = l0 + 377 - i;
            xbuf[XR0 + i] = (gr < L_IN) ? xb[gr] : 0.0f;
            int g2 = l0 + 376 - i;
            xbuf[XR1 + i] = (g2 < L_IN) ? xb[g2] : 0.0f;
        }
    }
    __syncthreads();

    const int mp  = w & 3;
    const int nh  = w >> 2;
    const int gid = lane >> 2;
    const int tig = lane & 3;
    const int par = gid & 1;        // parity of r (16*mt even)
    const int qq  = 1 - par;        // parity of rev index

    const int rA  = 32 * mp + gid;  // row of m-tile 2mp for this lane

    const float2* Xf = (const float2*)(xbuf + (par ? XF1 : XF0));
    const float2* Xr = (const float2*)(xbuf + (qq ? XR1 : XR0));

    float D[2][5][4];
    #pragma unroll
    for (int m = 0; m < 2; m++)
        #pragma unroll
        for (int n = 0; n < 5; n++)
            #pragma unroll
            for (int e = 0; e < 4; e++)
                D[m][n][e] = 0.0f;

    #pragma unroll 1
    for (int ks = 0; ks < KSTEPS; ks++) {
        const int k0 = 16 * ks + 2 * tig;
        const int vb = (rA - par + k0) >> 1;            // fwd f2 word of v = rA+k0
        const int ub = (127 - rA + k0 - 24 - qq) >> 1;  // rev f2 word of u-24

        float2 F0 = Xf[vb],      F1 = Xf[vb + 4],  F2 = Xf[vb + 8];
        float2 F3 = Xf[vb + 12], F4 = Xf[vb + 16];
        float2 R0 = Xr[ub],      R1 = Xr[ub + 4],  R2 = Xr[ub + 8];
        float2 R3 = Xr[ub + 12], R4 = Xr[ub + 16];

        uint4 Ah0, Al0, Ah1, Al1;
        mk_frag(Ah0.x, Al0.x, F0, R3);   // (r,   k0)
        mk_frag(Ah0.y, Al0.y, F1, R2);   // (r+8, k0)
        mk_frag(Ah0.z, Al0.z, F1, R4);   // (r,   k0+8)
        mk_frag(Ah0.w, Al0.w, F2, R3);   // (r+8, k0+8)
        mk_frag(Ah1.x, Al1.x, F2, R1);
        mk_frag(Ah1.y, Al1.y, F3, R0);
        mk_frag(Ah1.z, Al1.z, F3, R2);
        mk_frag(Ah1.w, Al1.w, F4, R1);

        const uint2* __restrict__ Hp = &Hfrag_g[ks][5 * nh][lane];
        #pragma unroll
        for (int n = 0; n < 5; n++) {
            uint2 Bf = Hp[n * 32];          // LDG.64, L1/L2-hot
            mma16816(D[0][n], Ah0.x, Ah0.y, Ah0.z, Ah0.w, Bf.x, Bf.y);  // h*sh
            mma16816(D[0][n], Al0.x, Al0.y, Al0.z, Al0.w, Bf.x, Bf.y);  // h*sl
            mma16816(D[1][n], Ah1.x, Ah1.y, Ah1.z, Ah1.w, Bf.x, Bf.y);
            mma16816(D[1][n], Al1.x, Al1.y, Al1.z, Al1.w, Bf.x, Bf.y);
        }
    }

    // ---- store (R11-style direct): m-tile (2mp+m): l = l0+16(2mp+m)+rp (+8) ----
    const int rp = lane >> 2;
    const int q  = lane & 3;
    float* ob = out + (size_t)b * N_FILT * L_OUT;
    #pragma unroll
    for (int m = 0; m < 2; m++) {
        const int l = l0 + 16 * (2 * mp + m) + rp;
        #pragma unroll
        for (int n = 0; n < 5; n++) {
            int f = (5 * nh + n) * 8 + q * 2;
            if (l < L_OUT) {
                ob[(size_t)f * L_OUT + l]       = D[m][n][0];
                ob[(size_t)(f + 1) * L_OUT + l] = D[m][n][1];
            }
            if (l + 8 < L_OUT) {
                ob[(size_t)f * L_OUT + l + 8]       = D[m][n][2];
                ob[(size_t)(f + 1) * L_OUT + l + 8] = D[m][n][3];
            }
        }
    }
}

// ---------------------------------------------------------------------------
extern "C" void kernel_launch(void* const* d_in, const int* in_sizes, int n_in,
                              void* d_out, int out_size)
{
    const float* x       = (const float*)d_in[0];
    const float* norm_f1 = (const float*)d_in[1];
    const float* norm_f2 = (const float*)d_in[2];
    const float* ampl    = (const float*)d_in[3];
    float* out = (float*)d_out;

    cudaFuncSetAttribute(sinc_conv_kernel,
                         cudaFuncAttributeMaxDynamicSharedMemorySize,
                         (int)sizeof(Smem));

    build_filters_kernel<<<N_FILT, 128>>>(norm_f1, norm_f2, ampl);

    dim3 grid(NLT, BATCH);   // (249, 32)
    sinc_conv_kernel<<<grid, THREADS, sizeof(Smem)>>>(x, out);
}